// round 16
// baseline (speedup 1.0000x reference)
#include <cuda_runtime.h>
#include <cstdint>

// ============================================================================
// InvConv1x1Conditional on sm_100 (base PTX -> mma.sync HMMA + cp.async).
//   out     = inp + E_b @ inp     (E = pooled@w_lin^T + b_lin, W = I + E)
//   log_det = HW * mean_b [ tr(E) - tr(E^2)/2 + tr(E^3)/3 ]
// ZERO __device__ globals. Scratch inside d_out:
//   packed E_b bf16 (8192 u32) at (b,tile0) footprint: u32 p=o*64+iu at float
//       b*CHW + (p>>7)*4096 + (p&127)       [ch<64, hw<128 of batch b]
//   pool/diag/partials/counter at batch-4 ch64..66 (never touched by E).
// k_main v2: E via cp.async (full 32 KB); inp staged as bf16 pairs in smem
// (LDG fp32 -> cvt -> STS, register-prefetched per 32-ch chunk); epilogue
// re-reads inp from global (L2-hot). smem 69.6 KB, 2 CTAs/SM, LDS halved.
// Split: g1 = tiles 1..31 (never write hw<128), g2 = tile 0.
// ============================================================================

static constexpr int BB = 32, CC = 128, HWSZ = 4096;
static constexpr int CHW  = CC * HWSZ;       // 524288
static constexpr int NOUT = BB * CHW;        // 16777216
static constexpr int OFF_SCRATCH = 4 * CHW + 64 * HWSZ;   // batch 4, ch 64

#define CVT_BF16X2_F32(result, a, b) \
    asm("cvt.rn.satfinite.bf16x2.f32 %0, %1, %2;" : "=r"(result) : "f"(b), "f"(a))
#define F32_TO_BF16U(us, f) \
    asm("cvt.rn.bf16.f32 %0, %1;" : "=h"(us) : "f"(f))

#define MMA16816(d0,d1,d2,d3, a0,a1,a2,a3, b0,b1) \
    asm volatile("mma.sync.aligned.m16n8k16.row.col.f32.bf16.bf16.f32 " \
                 "{%0,%1,%2,%3}, {%4,%5,%6,%7}, {%8,%9}, {%0,%1,%2,%3};" \
                 : "+f"(d0), "+f"(d1), "+f"(d2), "+f"(d3) \
                 : "r"(a0), "r"(a1), "r"(a2), "r"(a3), "r"(b0), "r"(b1))

#define CP_ASYNC16(dst_u32addr, src_ptr) \
    asm volatile("cp.async.cg.shared.global [%0], [%1], 16;" \
                 :: "r"(dst_u32addr), "l"(src_ptr) : "memory")
#define CP_COMMIT() asm volatile("cp.async.commit_group;" ::: "memory")
#define CP_WAIT(N)  asm volatile("cp.async.wait_group %0;" :: "n"(N) : "memory")

__device__ __forceinline__ float bf_lo(uint32_t w) { return __uint_as_float(w << 16); }
__device__ __forceinline__ float bf_hi(uint32_t w) { return __uint_as_float(w & 0xFFFF0000u); }
__device__ __forceinline__ uint32_t smem_u32(const void* p) {
    uint32_t a;
    asm("{ .reg .u64 t; cvta.to.shared.u64 t, %1; cvt.u32.u64 %0, t; }" : "=r"(a) : "l"(p));
    return a;
}

// ============================================================================
// K1: pooled[b][c] = mean_hw condition[b,c,:]; block 0 zeroes the counter.
// ============================================================================
__global__ void __launch_bounds__(128, 1) k_pool(const float* __restrict__ cond,
                                                 float* __restrict__ pool,
                                                 int* __restrict__ counter) {
    const int b = blockIdx.x >> 7, c = blockIdx.x & 127;
    const int t = threadIdx.x;
    if (blockIdx.x == 0 && t == 0) *counter = 0;
    const float4* p = (const float4*)(cond + (size_t)(b * CC + c) * HWSZ);
    float s = 0.f;
#pragma unroll
    for (int k = 0; k < 8; k++) {
        float4 v = p[t + k * 128];
        s += (v.x + v.y) + (v.z + v.w);
    }
#pragma unroll
    for (int o = 16; o; o >>= 1) s += __shfl_xor_sync(0xFFFFFFFFu, s, o);
    __shared__ float ws[4];
    if ((t & 31) == 0) ws[t >> 5] = s;
    __syncthreads();
    if (t == 0)
        pool[b * CC + c] = (ws[0] + ws[1] + ws[2] + ws[3]) * (1.0f / HWSZ);
}

// ============================================================================
// K2: E[b][r] = dot(pooled[b,:], w_lin[r,:]) + b_lin[r]; packed bf16 + diag.
// ============================================================================
__global__ void __launch_bounds__(256, 1) k_wmat(const float* __restrict__ w_lin,
                                                 const float* __restrict__ b_lin,
                                                 const float* __restrict__ pool,
                                                 float* __restrict__ outbase,
                                                 float* __restrict__ diag) {
    __shared__ float ws[32 * 132];
    __shared__ float ps[32 * 132];
    const int t = threadIdx.x;
    const int r0 = blockIdx.x * 32;

    for (int idx = t; idx < 4096; idx += 256) {
        const int rr = idx >> 7, k = idx & 127;
        ws[rr * 132 + k] = w_lin[(size_t)(r0 + rr) * CC + k];
        ps[rr * 132 + k] = pool[rr * CC + k];
    }
    __syncthreads();

    const int b = t >> 3, rl = t & 7;
    float wa0 = 0.f, wa1 = 0.f, wa2 = 0.f, wa3 = 0.f;
#pragma unroll 4
    for (int k = 0; k < 128; k++) {
        const float pv = ps[b * 132 + k];
        wa0 += pv * ws[(rl     ) * 132 + k];
        wa1 += pv * ws[(rl +  8) * 132 + k];
        wa2 += pv * ws[(rl + 16) * 132 + k];
        wa3 += pv * ws[(rl + 24) * 132 + k];
    }

    unsigned short* outU16 = (unsigned short*)outbase;
#define WOUT(J, WA) do { \
    const int r = r0 + rl + 8 * (J); \
    const float val = (WA) + b_lin[r]; \
    const int o = r >> 7, i = r & 127; \
    const int p = o * 64 + (i >> 1); \
    unsigned short us; F32_TO_BF16U(us, val); \
    outU16[2 * ((size_t)b * CHW + ((p >> 7) << 12) + (p & 127)) + (i & 1)] = us; \
    if (o == i) diag[b * CC + o] = val; } while (0)
    WOUT(0, wa0); WOUT(1, wa1); WOUT(2, wa2); WOUT(3, wa3);
#undef WOUT
}

// ============================================================================
// K3: fused G-rows + traces + last-block finalize -> out[NOUT].
// smem = Es 32768 + Arow 16384 = 49152 B; red/s_old aliased onto Arow.
// ============================================================================
__global__ void __launch_bounds__(256, 1) k_cond(const float* __restrict__ outbase,
                                                 const float* __restrict__ diag,
                                                 float* __restrict__ partials,
                                                 int* __restrict__ counter,
                                                 float* __restrict__ out,
                                                 int out_size) {
    __shared__ uint32_t Es[8192];
    __shared__ float Arow[32 * 128];
    float* red = Arow;                       // aliased (Arow fully consumed)
    int* s_oldp = (int*)(Arow + 8);          // aliased

    const int q = blockIdx.x, b = blockIdx.y;
    const int t = threadIdx.x;
    const int i0 = q * 32;
    const uint32_t* Ebp = (const uint32_t*)outbase + (size_t)b * CHW;

#pragma unroll
    for (int j = 0; j < 32; j++) {
        const int p = t + j * 256;
        Es[p] = Ebp[((p >> 7) << 12) + (p & 127)];
    }
    __syncthreads();
#pragma unroll
    for (int j = 0; j < 16; j++) {
        const int idx = t + j * 256;
        const int rr = idx >> 7, k = idx & 127;
        const uint32_t w = Es[(i0 + rr) * 64 + (k >> 1)];
        Arow[rr * 128 + k] = (k & 1) ? bf_hi(w) : bf_lo(w);
    }
    __syncthreads();

    const int j = t & 127, ib = t >> 7;
    const int jj = j >> 1, jodd = j & 1;

#define GDECL(M) float g##M = 0.f
    GDECL(0);  GDECL(1);  GDECL(2);  GDECL(3);
    GDECL(4);  GDECL(5);  GDECL(6);  GDECL(7);
    GDECL(8);  GDECL(9);  GDECL(10); GDECL(11);
    GDECL(12); GDECL(13); GDECL(14); GDECL(15);

#define GFMA(M) do { \
    const float4 _a = *(const float4*)&Arow[(ib + 2 * (M)) * 128 + k0]; \
    g##M += _a.x * bb0 + _a.y * bb1 + _a.z * bb2 + _a.w * bb3; } while (0)

#pragma unroll 2
    for (int k0 = 0; k0 < 128; k0 += 4) {
        const uint32_t w0 = Es[(k0 + 0) * 64 + jj];
        const uint32_t w1 = Es[(k0 + 1) * 64 + jj];
        const uint32_t w2 = Es[(k0 + 2) * 64 + jj];
        const uint32_t w3 = Es[(k0 + 3) * 64 + jj];
        const float bb0 = jodd ? bf_hi(w0) : bf_lo(w0);
        const float bb1 = jodd ? bf_hi(w1) : bf_lo(w1);
        const float bb2 = jodd ? bf_hi(w2) : bf_lo(w2);
        const float bb3 = jodd ? bf_hi(w3) : bf_lo(w3);
        GFMA(0);  GFMA(1);  GFMA(2);  GFMA(3);
        GFMA(4);  GFMA(5);  GFMA(6);  GFMA(7);
        GFMA(8);  GFMA(9);  GFMA(10); GFMA(11);
        GFMA(12); GFMA(13); GFMA(14); GFMA(15);
    }

    float pt2 = 0.f, pt3 = 0.f, pt1 = 0.f;
#define GTRACE(M) do { \
    const int _ig = i0 + ib + 2 * (M); \
    const uint32_t _wij = Es[_ig * 64 + jj]; \
    const float _eij = jodd ? bf_hi(_wij) : bf_lo(_wij); \
    const uint32_t _wji = Es[j * 64 + (_ig >> 1)]; \
    const float _eji = ib ? bf_hi(_wji) : bf_lo(_wji); \
    pt2 += _eij * _eji; pt3 += g##M * _eji; } while (0)
    GTRACE(0);  GTRACE(1);  GTRACE(2);  GTRACE(3);
    GTRACE(4);  GTRACE(5);  GTRACE(6);  GTRACE(7);
    GTRACE(8);  GTRACE(9);  GTRACE(10); GTRACE(11);
    GTRACE(12); GTRACE(13); GTRACE(14); GTRACE(15);
#undef GTRACE
#undef GFMA
#undef GDECL

    if (j == 0) {
#pragma unroll
        for (int m = 0; m < 16; m++) pt1 += diag[b * CC + i0 + ib + 2 * m];
    }

    float pl = pt1 - 0.5f * pt2 + (1.0f / 3.0f) * pt3;
#pragma unroll
    for (int o = 16; o; o >>= 1) pl += __shfl_xor_sync(0xFFFFFFFFu, pl, o);

    __syncthreads();                         // all Arow/Es reads done -> alias safe
    if ((t & 31) == 0) red[t >> 5] = pl;
    __syncthreads();

    if (t == 0) {
        float bp = 0.f;
#pragma unroll
        for (int w = 0; w < 8; w++) bp += red[w];
        partials[(b << 2) + q] = bp;
        __threadfence();
        *s_oldp = atomicAdd(counter, 1);
    }
    __syncthreads();

    if (*s_oldp == 127) {                    // last block finalizes
        __threadfence();
        float v = (t < 128) ? partials[t] : 0.f;
#pragma unroll
        for (int o = 16; o; o >>= 1) v += __shfl_xor_sync(0xFFFFFFFFu, v, o);
        __syncthreads();
        if ((t & 31) == 0) red[t >> 5] = v;
        __syncthreads();
        if (t == 0 && out_size > NOUT) {
            float a = 0.f;
#pragma unroll
            for (int w = 0; w < 8; w++) a += red[w];
            out[NOUT] = a * ((float)HWSZ / (float)BB);
        }
    }
}

// ============================================================================
// K5 v2: HMMA GEMM. E full bf16 in smem via cp.async; B staged bf16 via
// LDG->cvt->STS with register prefetch of the next 32-ch chunk.
// smem: As[128o][68 u32] + Bb[128n][68 u32] = 69632 B -> 2 CTAs/SM.
// Fragment loads: 2 LDS.32 each, conflict-free (bank = 4g+tig).
// Epilogue: out = inp(global, L2-hot) + acc.
// ============================================================================
static constexpr int PITCH = 68;                       // u32 per row
static constexpr int SMEM_MAIN = 2 * 128 * PITCH * 4;  // 69632 B

#define ACC(m,n,q) c_##m##_##n##_##q
#define DECL4(m,n) float ACC(m,n,0)=0.f, ACC(m,n,1)=0.f, ACC(m,n,2)=0.f, ACC(m,n,3)=0.f

#define LOADA(m,K) do { \
    const int _r0 = (wm + (m) * 16 + g) * PITCH + (K) * 8 + tig; \
    a##m##_0 = As[_r0]; a##m##_1 = As[_r0 + 8 * PITCH]; \
    a##m##_2 = As[_r0 + 4]; a##m##_3 = As[_r0 + 8 * PITCH + 4]; } while (0)

#define LOADF(q,nt,K) do { \
    const int _rn = (wn + (nt) * 8 + g) * PITCH + (K) * 8 + tig; \
    f##q##_0 = Bb[_rn]; f##q##_1 = Bb[_rn + 4]; } while (0)

#define MMAQ(m,q,n) MMA16816(ACC(m,n,0), ACC(m,n,1), ACC(m,n,2), ACC(m,n,3), \
                             a##m##_0, a##m##_1, a##m##_2, a##m##_3, \
                             f##q##_0, f##q##_1)

#define KSTEP(K) do { \
    LOADA(0,K); LOADA(1,K); \
    LOADF(0,0,K); LOADF(1,1,K); LOADF(2,2,K); LOADF(3,3,K); \
    MMAQ(0,0,0); MMAQ(1,0,0); MMAQ(0,1,1); MMAQ(1,1,1); \
    MMAQ(0,2,2); MMAQ(1,2,2); MMAQ(0,3,3); MMAQ(1,3,3); \
    LOADF(0,4,K); LOADF(1,5,K); LOADF(2,6,K); LOADF(3,7,K); \
    MMAQ(0,0,4); MMAQ(1,0,4); MMAQ(0,1,5); MMAQ(1,1,5); \
    MMAQ(0,2,6); MMAQ(1,2,6); MMAQ(0,3,7); MMAQ(1,3,7); } while (0)

#define COMPUTE(C) do { KSTEP(2 * (C)); KSTEP(2 * (C) + 1); } while (0)

// LDG prefetch of chunk C: this thread owns column nn, rows ip = 16C+th+2j
#define LDGB1(J) do { \
    const int _ip = _ip0 + 2 * (J); \
    pf##J##a = ibase[(size_t)(2 * _ip)     * HWSZ + nn]; \
    pf##J##b = ibase[(size_t)(2 * _ip + 1) * HWSZ + nn]; } while (0)
#define LDGB(C) do { const int _ip0 = 16 * (C) + th; \
    LDGB1(0); LDGB1(1); LDGB1(2); LDGB1(3); \
    LDGB1(4); LDGB1(5); LDGB1(6); LDGB1(7); } while (0)

#define STSB1(J) do { \
    uint32_t _pk; CVT_BF16X2_F32(_pk, pf##J##a, pf##J##b); \
    Bb[nn * PITCH + _ip0 + 2 * (J)] = _pk; } while (0)
#define STSB(C) do { const int _ip0 = 16 * (C) + th; \
    STSB1(0); STSB1(1); STSB1(2); STSB1(3); \
    STSB1(4); STSB1(5); STSB1(6); STSB1(7); } while (0)

#define EPI(m,nt) do { \
    const int _o0 = wm + (m) * 16 + g; \
    const int _hw = wn + (nt) * 8 + tig * 2; \
    const float2 _iv0 = *(const float2*)(ibase + (size_t)_o0 * HWSZ + _hw); \
    float2 _ov0; _ov0.x = _iv0.x + ACC(m,nt,0); _ov0.y = _iv0.y + ACC(m,nt,1); \
    *(float2*)(obase + (size_t)_o0 * HWSZ + _hw) = _ov0; \
    const float2 _iv1 = *(const float2*)(ibase + (size_t)(_o0 + 8) * HWSZ + _hw); \
    float2 _ov1; _ov1.x = _iv1.x + ACC(m,nt,2); _ov1.y = _iv1.y + ACC(m,nt,3); \
    *(float2*)(obase + (size_t)(_o0 + 8) * HWSZ + _hw) = _ov1; } while (0)

__global__ void __launch_bounds__(256) k_main(const float* __restrict__ inp,
                                              float* __restrict__ out,
                                              int tile_base) {
    extern __shared__ uint32_t sm[];
    uint32_t* As = sm;                   // E bf16 pairs [o][iu], pitch 68
    uint32_t* Bb = sm + 128 * PITCH;     // inp bf16 pairs [n][ip], pitch 68
    const uint32_t smemA = smem_u32(sm);

    const int tile = tile_base + blockIdx.x;
    const int b = blockIdx.y;
    const int hw0 = tile << 7;
    const int t = threadIdx.x;
    const int warp = t >> 5, lane = t & 31;
    const int g = lane >> 2, tig = lane & 3;
    const int wm = (warp >> 1) * 32;
    const int wn = (warp & 1) * 64;
    const int nn = t & 127, th = t >> 7;

    const float* ibase = inp + (size_t)b * CHW + hw0;
    const uint32_t* ebf = (const uint32_t*)out + (size_t)b * CHW;

    // E: full 32 KB via cp.async (8 x 16B per thread)
#pragma unroll
    for (int j = 0; j < 8; j++) {
        const int s = t + j * 256;           // 0..2047 16B units
        const int o = s >> 4, c4 = s & 15;
        const int p = o * 64 + c4 * 4;
        const uint32_t* _sa = ebf + ((p >> 7) << 12) + (p & 127);
        const uint32_t _da = smemA + (uint32_t)(o * PITCH + c4 * 4) * 4;
        CP_ASYNC16(_da, _sa);
    }
    CP_COMMIT();

    float pf0a, pf0b, pf1a, pf1b, pf2a, pf2b, pf3a, pf3b;
    float pf4a, pf4b, pf5a, pf5b, pf6a, pf6b, pf7a, pf7b;
    uint32_t a0_0, a0_1, a0_2, a0_3, a1_0, a1_1, a1_2, a1_3;
    uint32_t f0_0, f0_1, f1_0, f1_1, f2_0, f2_1, f3_0, f3_1;
    DECL4(0,0); DECL4(0,1); DECL4(0,2); DECL4(0,3);
    DECL4(0,4); DECL4(0,5); DECL4(0,6); DECL4(0,7);
    DECL4(1,0); DECL4(1,1); DECL4(1,2); DECL4(1,3);
    DECL4(1,4); DECL4(1,5); DECL4(1,6); DECL4(1,7);

    LDGB(0);
    STSB(0);
    LDGB(1);                                 // in flight during COMPUTE(0)
    CP_WAIT(0);                              // E landed
    __syncthreads();

    COMPUTE(0);
    STSB(1); LDGB(2);
    __syncthreads();

    COMPUTE(1);
    STSB(2); LDGB(3);
    __syncthreads();

    COMPUTE(2);
    STSB(3);
    __syncthreads();

    COMPUTE(3);

    float* obase = out + (size_t)b * CHW + hw0;
    EPI(0,0); EPI(0,1); EPI(0,2); EPI(0,3);
    EPI(0,4); EPI(0,5); EPI(0,6); EPI(0,7);
    EPI(1,0); EPI(1,1); EPI(1,2); EPI(1,3);
    EPI(1,4); EPI(1,5); EPI(1,6); EPI(1,7);
}

// ============================================================================
// launch
// ============================================================================
extern "C" void kernel_launch(void* const* d_in, const int* in_sizes, int n_in,
                              void* d_out, int out_size) {
    const float* inp   = (const float*)d_in[0];
    const float* cond  = (const float*)d_in[1];
    const float* w_lin = (const float*)d_in[2];
    const float* b_lin = (const float*)d_in[3];
    float* out = (float*)d_out;

    float* pool     = out + OFF_SCRATCH;              // batch4 ch64
    float* diag     = out + OFF_SCRATCH + HWSZ;       // batch4 ch65
    float* partials = out + OFF_SCRATCH + 2 * HWSZ;   // batch4 ch66
    int*   counter  = (int*)(partials + 512);

    cudaFuncSetAttribute(k_main, cudaFuncAttributeMaxDynamicSharedMemorySize, SMEM_MAIN);

    k_pool <<<BB * CC, 128>>>(cond, pool, counter);
    k_wmat <<<512, 256>>>(w_lin, b_lin, pool, out, diag);
    {
        dim3 gc(4, BB);
        k_cond <<<gc, 256>>>(out, diag, partials, counter, out, out_size);
    }
    {
        dim3 g1(31, BB);                 // tiles 1..31 (never write hw<128)
        k_main <<<g1, 256, SMEM_MAIN>>>(inp, out, 1);
        dim3 g2(1, BB);                  // tile 0 (reads own E before writing)
        k_main <<<g2, 256, SMEM_MAIN>>>(inp, out, 0);
    }
}

// round 17
// speedup vs baseline: 1.1588x; 1.1588x over previous
#include <cuda_runtime.h>
#include <cstdint>

// ============================================================================
// InvConv1x1Conditional on sm_100 (base PTX -> mma.sync HMMA + cp.async).
//   out     = inp + E_b @ inp     (E = pooled@w_lin^T + b_lin, W = I + E)
//   log_det = HW * mean_b [ tr(E) - tr(E^2)/2 + tr(E^3)/3 ]
// ZERO __device__ globals. Scratch inside d_out:
//   E_b bf16 in MMA FRAGMENT ORDER (8192 u32) at (b,tile0) footprint:
//       u32 q at float b*CHW + (q>>7)*4096 + (q&127)   [ch<64, hw<128]
//       q = ((og*8+K)*32+lane)*4+slot; A fragment = ONE LDS.128
//   E linear u16 copy (for k_cond) at batch-3 ch64..127 (consumed pre-k_main)
//   pool/diag/partials/counter at batch-4 ch64..66.
// k_main (round-15 B path): inp staged fp32 via cp.async 2-deep chunk
// pipeline; epilogue adds inp from smem. A: linear 32KB cp.async + LDS.128.
// Split: g1 = tiles 1..31 (never write hw<128), g2 = tile 0 (self-ordered).
// ============================================================================

static constexpr int BB = 32, CC = 128, HWSZ = 4096;
static constexpr int CHW  = CC * HWSZ;       // 524288
static constexpr int NOUT = BB * CHW;        // 16777216
static constexpr int OFF_SCRATCH = 4 * CHW + 64 * HWSZ;   // batch 4, ch 64
static constexpr int OFF_ECOPY   = 3 * CHW + 64 * HWSZ;   // batch 3, ch 64

#define CVT_BF16X2_F32(result, a, b) \
    asm("cvt.rn.satfinite.bf16x2.f32 %0, %1, %2;" : "=r"(result) : "f"(b), "f"(a))
#define F32_TO_BF16U(us, f) \
    asm("cvt.rn.bf16.f32 %0, %1;" : "=h"(us) : "f"(f))

#define MMA16816(d0,d1,d2,d3, a0,a1,a2,a3, b0,b1) \
    asm volatile("mma.sync.aligned.m16n8k16.row.col.f32.bf16.bf16.f32 " \
                 "{%0,%1,%2,%3}, {%4,%5,%6,%7}, {%8,%9}, {%0,%1,%2,%3};" \
                 : "+f"(d0), "+f"(d1), "+f"(d2), "+f"(d3) \
                 : "r"(a0), "r"(a1), "r"(a2), "r"(a3), "r"(b0), "r"(b1))

#define CP_ASYNC16(dst_u32addr, src_ptr) \
    asm volatile("cp.async.cg.shared.global [%0], [%1], 16;" \
                 :: "r"(dst_u32addr), "l"(src_ptr) : "memory")
#define CP_COMMIT() asm volatile("cp.async.commit_group;" ::: "memory")
#define CP_WAIT(N)  asm volatile("cp.async.wait_group %0;" :: "n"(N) : "memory")

__device__ __forceinline__ float bf_lo(uint32_t w) { return __uint_as_float(w << 16); }
__device__ __forceinline__ float bf_hi(uint32_t w) { return __uint_as_float(w & 0xFFFF0000u); }
__device__ __forceinline__ uint32_t smem_u32(const void* p) {
    uint32_t a;
    asm("{ .reg .u64 t; cvta.to.shared.u64 t, %1; cvt.u32.u64 %0, t; }" : "=r"(a) : "l"(p));
    return a;
}

// ============================================================================
// K1: pooled[b][c] = mean_hw condition[b,c,:]; block 0 zeroes the counter.
// ============================================================================
__global__ void __launch_bounds__(128, 1) k_pool(const float* __restrict__ cond,
                                                 float* __restrict__ pool,
                                                 int* __restrict__ counter) {
    const int b = blockIdx.x >> 7, c = blockIdx.x & 127;
    const int t = threadIdx.x;
    if (blockIdx.x == 0 && t == 0) *counter = 0;
    const float4* p = (const float4*)(cond + (size_t)(b * CC + c) * HWSZ);
    float s = 0.f;
#pragma unroll
    for (int k = 0; k < 8; k++) {
        float4 v = p[t + k * 128];
        s += (v.x + v.y) + (v.z + v.w);
    }
#pragma unroll
    for (int o = 16; o; o >>= 1) s += __shfl_xor_sync(0xFFFFFFFFu, s, o);
    __shared__ float ws[4];
    if ((t & 31) == 0) ws[t >> 5] = s;
    __syncthreads();
    if (t == 0)
        pool[b * CC + c] = (ws[0] + ws[1] + ws[2] + ws[3]) * (1.0f / HWSZ);
}

// ============================================================================
// K2: E[b][r] = dot(pooled[b,:], w_lin[r,:]) + b_lin[r].
// Stores: (a) fragment-order bf16 at (b,tile0) footprint, (b) linear u16 copy
// for k_cond at batch-3 ch64+, (c) fp32 diag.
// ============================================================================
__global__ void __launch_bounds__(256, 1) k_wmat(const float* __restrict__ w_lin,
                                                 const float* __restrict__ b_lin,
                                                 const float* __restrict__ pool,
                                                 float* __restrict__ outbase,
                                                 float* __restrict__ diag) {
    __shared__ float ws[32 * 132];
    __shared__ float ps[32 * 132];
    const int t = threadIdx.x;
    const int r0 = blockIdx.x * 32;

    for (int idx = t; idx < 4096; idx += 256) {
        const int rr = idx >> 7, k = idx & 127;
        ws[rr * 132 + k] = w_lin[(size_t)(r0 + rr) * CC + k];
        ps[rr * 132 + k] = pool[rr * CC + k];
    }
    __syncthreads();

    const int b = t >> 3, rl = t & 7;
    float wa0 = 0.f, wa1 = 0.f, wa2 = 0.f, wa3 = 0.f;
#pragma unroll 4
    for (int k = 0; k < 128; k++) {
        const float pv = ps[b * 132 + k];
        wa0 += pv * ws[(rl     ) * 132 + k];
        wa1 += pv * ws[(rl +  8) * 132 + k];
        wa2 += pv * ws[(rl + 16) * 132 + k];
        wa3 += pv * ws[(rl + 24) * 132 + k];
    }

    unsigned short* outU16  = (unsigned short*)outbase;
    unsigned short* ecopy16 = (unsigned short*)(outbase + OFF_ECOPY);
#define WOUT(J, WA) do { \
    const int r = r0 + rl + 8 * (J); \
    const float val = (WA) + b_lin[r]; \
    const int o = r >> 7, i = r & 127; \
    unsigned short us; F32_TO_BF16U(us, val); \
    ecopy16[(size_t)b * 16384 + r] = us; \
    const int iu = i >> 1; \
    const int lane = ((o & 7) << 2) | (iu & 3); \
    const int slot = (((iu & 7) >= 4) ? 2 : 0) + (((o & 15) >= 8) ? 1 : 0); \
    const int q = (((o >> 4) * 8 + (iu >> 3)) * 32 + lane) * 4 + slot; \
    outU16[2 * ((size_t)b * CHW + ((q >> 7) << 12) + (q & 127)) + (i & 1)] = us; \
    if (o == i) diag[b * CC + o] = val; } while (0)
    WOUT(0, wa0); WOUT(1, wa1); WOUT(2, wa2); WOUT(3, wa3);
#undef WOUT
}

// ============================================================================
// K3: fused G-rows + traces + last-block finalize -> out[NOUT].
// Reads the LINEAR u16 E copy (batch-3 ch64+). smem 49152 B; red aliased.
// ============================================================================
__global__ void __launch_bounds__(256, 1) k_cond(const float* __restrict__ outbase,
                                                 const float* __restrict__ diag,
                                                 float* __restrict__ partials,
                                                 int* __restrict__ counter,
                                                 float* __restrict__ out,
                                                 int out_size) {
    __shared__ uint32_t Es[8192];
    __shared__ float Arow[32 * 128];
    float* red = Arow;
    int* s_oldp = (int*)(Arow + 8);

    const int q = blockIdx.x, b = blockIdx.y;
    const int t = threadIdx.x;
    const int i0 = q * 32;
    const uint32_t* Ebp = (const uint32_t*)(outbase + OFF_ECOPY) + (size_t)b * 8192;

#pragma unroll
    for (int j = 0; j < 32; j++) {
        const int p = t + j * 256;
        Es[p] = Ebp[p];                      // linear, coalesced
    }
    __syncthreads();
#pragma unroll
    for (int j = 0; j < 16; j++) {
        const int idx = t + j * 256;
        const int rr = idx >> 7, k = idx & 127;
        const uint32_t w = Es[(i0 + rr) * 64 + (k >> 1)];
        Arow[rr * 128 + k] = (k & 1) ? bf_hi(w) : bf_lo(w);
    }
    __syncthreads();

    const int j = t & 127, ib = t >> 7;
    const int jj = j >> 1, jodd = j & 1;

#define GDECL(M) float g##M = 0.f
    GDECL(0);  GDECL(1);  GDECL(2);  GDECL(3);
    GDECL(4);  GDECL(5);  GDECL(6);  GDECL(7);
    GDECL(8);  GDECL(9);  GDECL(10); GDECL(11);
    GDECL(12); GDECL(13); GDECL(14); GDECL(15);

#define GFMA(M) do { \
    const float4 _a = *(const float4*)&Arow[(ib + 2 * (M)) * 128 + k0]; \
    g##M += _a.x * bb0 + _a.y * bb1 + _a.z * bb2 + _a.w * bb3; } while (0)

#pragma unroll 2
    for (int k0 = 0; k0 < 128; k0 += 4) {
        const uint32_t w0 = Es[(k0 + 0) * 64 + jj];
        const uint32_t w1 = Es[(k0 + 1) * 64 + jj];
        const uint32_t w2 = Es[(k0 + 2) * 64 + jj];
        const uint32_t w3 = Es[(k0 + 3) * 64 + jj];
        const float bb0 = jodd ? bf_hi(w0) : bf_lo(w0);
        const float bb1 = jodd ? bf_hi(w1) : bf_lo(w1);
        const float bb2 = jodd ? bf_hi(w2) : bf_lo(w2);
        const float bb3 = jodd ? bf_hi(w3) : bf_lo(w3);
        GFMA(0);  GFMA(1);  GFMA(2);  GFMA(3);
        GFMA(4);  GFMA(5);  GFMA(6);  GFMA(7);
        GFMA(8);  GFMA(9);  GFMA(10); GFMA(11);
        GFMA(12); GFMA(13); GFMA(14); GFMA(15);
    }

    float pt2 = 0.f, pt3 = 0.f, pt1 = 0.f;
#define GTRACE(M) do { \
    const int _ig = i0 + ib + 2 * (M); \
    const uint32_t _wij = Es[_ig * 64 + jj]; \
    const float _eij = jodd ? bf_hi(_wij) : bf_lo(_wij); \
    const uint32_t _wji = Es[j * 64 + (_ig >> 1)]; \
    const float _eji = ib ? bf_hi(_wji) : bf_lo(_wji); \
    pt2 += _eij * _eji; pt3 += g##M * _eji; } while (0)
    GTRACE(0);  GTRACE(1);  GTRACE(2);  GTRACE(3);
    GTRACE(4);  GTRACE(5);  GTRACE(6);  GTRACE(7);
    GTRACE(8);  GTRACE(9);  GTRACE(10); GTRACE(11);
    GTRACE(12); GTRACE(13); GTRACE(14); GTRACE(15);
#undef GTRACE
#undef GFMA
#undef GDECL

    if (j == 0) {
#pragma unroll
        for (int m = 0; m < 16; m++) pt1 += diag[b * CC + i0 + ib + 2 * m];
    }

    float pl = pt1 - 0.5f * pt2 + (1.0f / 3.0f) * pt3;
#pragma unroll
    for (int o = 16; o; o >>= 1) pl += __shfl_xor_sync(0xFFFFFFFFu, pl, o);

    __syncthreads();
    if ((t & 31) == 0) red[t >> 5] = pl;
    __syncthreads();

    if (t == 0) {
        float bp = 0.f;
#pragma unroll
        for (int w = 0; w < 8; w++) bp += red[w];
        partials[(b << 2) + q] = bp;
        __threadfence();
        *s_oldp = atomicAdd(counter, 1);
    }
    __syncthreads();

    if (*s_oldp == 127) {
        __threadfence();
        float v = (t < 128) ? partials[t] : 0.f;
#pragma unroll
        for (int o = 16; o; o >>= 1) v += __shfl_xor_sync(0xFFFFFFFFu, v, o);
        __syncthreads();
        if ((t & 31) == 0) red[t >> 5] = v;
        __syncthreads();
        if (t == 0 && out_size > NOUT) {
            float a = 0.f;
#pragma unroll
            for (int w = 0; w < 8; w++) a += red[w];
            out[NOUT] = a * ((float)HWSZ / (float)BB);
        }
    }
}

// ============================================================================
// K5: HMMA GEMM. A = E fragment-order in smem (linear 32KB via cp.async,
// ONE LDS.128 per fragment). B = inp fp32 staged via cp.async 2-deep chunk
// pipeline (round-15 path); epilogue adds inp from smem.
// smem: As 32768 + BsF 67584 = 100352 B -> 2 CTAs/SM.
// ============================================================================
static constexpr int SMEM_MAIN = 32768 + 67584;     // 100352 B

#define ACC(m,n,q) c_##m##_##n##_##q
#define DECL4(m,n) float ACC(m,n,0)=0.f, ACC(m,n,1)=0.f, ACC(m,n,2)=0.f, ACC(m,n,3)=0.f

// A fragment: one 16B vector at ((og*8+K)*32+lane)*4
#define LOADA(m,K) do { \
    const uint4 _av = *(const uint4*)&As[((((wm >> 4) + (m)) * 8 + (K)) * 32 + lane) * 4]; \
    a##m##_0 = _av.x; a##m##_1 = _av.y; a##m##_2 = _av.z; a##m##_3 = _av.w; } while (0)

#define LOADF(q,nt,C,KL) do { \
    const int _n = wn + (nt) * 8 + g; \
    const int _c = (C) * 32 + 2 * ((KL) * 8 + tig); \
    const float _x0 = BsF[(_c    ) * 132 + _n]; \
    const float _x1 = BsF[(_c + 1) * 132 + _n]; \
    const float _y0 = BsF[(_c + 8) * 132 + _n]; \
    const float _y1 = BsF[(_c + 9) * 132 + _n]; \
    CVT_BF16X2_F32(f##q##_0, _x0, _x1); \
    CVT_BF16X2_F32(f##q##_1, _y0, _y1); } while (0)

#define MMAQ(m,q,n) MMA16816(ACC(m,n,0), ACC(m,n,1), ACC(m,n,2), ACC(m,n,3), \
                             a##m##_0, a##m##_1, a##m##_2, a##m##_3, \
                             f##q##_0, f##q##_1)

#define KSTEP_C(C,KL) do { \
    LOADA(0, 2 * (C) + (KL)); LOADA(1, 2 * (C) + (KL)); \
    LOADF(0,0,C,KL); LOADF(1,1,C,KL); LOADF(2,2,C,KL); LOADF(3,3,C,KL); \
    MMAQ(0,0,0); MMAQ(1,0,0); MMAQ(0,1,1); MMAQ(1,1,1); \
    MMAQ(0,2,2); MMAQ(1,2,2); MMAQ(0,3,3); MMAQ(1,3,3); \
    LOADF(0,4,C,KL); LOADF(1,5,C,KL); LOADF(2,6,C,KL); LOADF(3,7,C,KL); \
    MMAQ(0,0,4); MMAQ(1,0,4); MMAQ(0,1,5); MMAQ(1,1,5); \
    MMAQ(0,2,6); MMAQ(1,2,6); MMAQ(0,3,7); MMAQ(1,3,7); } while (0)

#define CHUNK_COMPUTE(C) do { KSTEP_C(C,0); KSTEP_C(C,1); } while (0)

// B chunk C: 32 channels x 128 hw fp32 -> BsF[(ch)*132 + hw]
#define ISSUE_B(C) do { \
    _Pragma("unroll") \
    for (int qq = 0; qq < 4; qq++) { \
        const int gi = t + qq * 256; \
        const int chp = gi >> 5, w = gi & 31; \
        const int ch = (C) * 32 + chp; \
        const float* _sb = ibase + (size_t)ch * HWSZ + 4 * w; \
        const uint32_t _db = smemB + (ch * 132 + 4 * w) * 4; \
        CP_ASYNC16(_db, _sb); \
    } } while (0)

#define EPI(m,nt) do { \
    const int _o0 = wm + (m) * 16 + g; \
    const int _hw = wn + (nt) * 8 + tig * 2; \
    const float _i00 = BsF[_o0 * 132 + _hw],       _i01 = BsF[_o0 * 132 + _hw + 1]; \
    const float _i10 = BsF[(_o0 + 8) * 132 + _hw], _i11 = BsF[(_o0 + 8) * 132 + _hw + 1]; \
    float2 _ov0; _ov0.x = _i00 + ACC(m,nt,0); _ov0.y = _i01 + ACC(m,nt,1); \
    *(float2*)(obase + (size_t)_o0 * HWSZ + _hw) = _ov0; \
    float2 _ov1; _ov1.x = _i10 + ACC(m,nt,2); _ov1.y = _i11 + ACC(m,nt,3); \
    *(float2*)(obase + (size_t)(_o0 + 8) * HWSZ + _hw) = _ov1; } while (0)

__global__ void __launch_bounds__(256) k_main(const float* __restrict__ inp,
                                              float* __restrict__ out,
                                              int tile_base) {
    extern __shared__ uint32_t sm[];
    uint32_t* As = sm;                         // 8192 u32, fragment order
    float* BsF = (float*)(sm + 8192);          // 128 ch x 132 pitch fp32
    const uint32_t smemA = smem_u32(sm);
    const uint32_t smemB = smemA + 32768;

    const int tile = tile_base + blockIdx.x;
    const int b = blockIdx.y;
    const int hw0 = tile << 7;
    const int t = threadIdx.x;
    const int warp = t >> 5, lane = t & 31;
    const int g = lane >> 2, tig = lane & 3;
    const int wm = (warp >> 1) * 32;
    const int wn = (warp & 1) * 64;

    const float* ibase = inp + (size_t)b * CHW + hw0;
    const uint32_t* ebf = (const uint32_t*)out + (size_t)b * CHW;

    uint32_t a0_0, a0_1, a0_2, a0_3, a1_0, a1_1, a1_2, a1_3;
    uint32_t f0_0, f0_1, f1_0, f1_1, f2_0, f2_1, f3_0, f3_1;
    DECL4(0,0); DECL4(0,1); DECL4(0,2); DECL4(0,3);
    DECL4(0,4); DECL4(0,5); DECL4(0,6); DECL4(0,7);
    DECL4(1,0); DECL4(1,1); DECL4(1,2); DECL4(1,3);
    DECL4(1,4); DECL4(1,5); DECL4(1,6); DECL4(1,7);

    // E: 32 KB linear fragment layout (8 x 16B per thread)
#pragma unroll
    for (int j = 0; j < 8; j++) {
        const int s = t + j * 256;              // 16B unit, q4 = s*4
        const int q4 = s * 4;
        const uint32_t* _sa = ebf + ((q4 >> 7) << 12) + (q4 & 127);
        CP_ASYNC16(smemA + (uint32_t)s * 16, _sa);
    }
    ISSUE_B(0); CP_COMMIT();                    // group: E + B0
    ISSUE_B(1); CP_COMMIT();

    CP_WAIT(1); __syncthreads();                // E + B0 ready
    ISSUE_B(2); CP_COMMIT();
    CHUNK_COMPUTE(0);

    CP_WAIT(1); __syncthreads();                // B1 ready
    ISSUE_B(3); CP_COMMIT();
    CHUNK_COMPUTE(1);

    CP_WAIT(1); __syncthreads();                // B2 ready
    CHUNK_COMPUTE(2);

    CP_WAIT(0); __syncthreads();                // B3 ready
    CHUNK_COMPUTE(3);

    float* obase = out + (size_t)b * CHW + hw0;
    EPI(0,0); EPI(0,1); EPI(0,2); EPI(0,3);
    EPI(0,4); EPI(0,5); EPI(0,6); EPI(0,7);
    EPI(1,0); EPI(1,1); EPI(1,2); EPI(1,3);
    EPI(1,4); EPI(1,5); EPI(1,6); EPI(1,7);
}

// ============================================================================
// launch
// ============================================================================
extern "C" void kernel_launch(void* const* d_in, const int* in_sizes, int n_in,
                              void* d_out, int out_size) {
    const float* inp   = (const float*)d_in[0];
    const float* cond  = (const float*)d_in[1];
    const float* w_lin = (const float*)d_in[2];
    const float* b_lin = (const float*)d_in[3];
    float* out = (float*)d_out;

    float* pool     = out + OFF_SCRATCH;              // batch4 ch64
    float* diag     = out + OFF_SCRATCH + HWSZ;       // batch4 ch65
    float* partials = out + OFF_SCRATCH + 2 * HWSZ;   // batch4 ch66
    int*   counter  = (int*)(partials + 512);

    cudaFuncSetAttribute(k_main, cudaFuncAttributeMaxDynamicSharedMemorySize, SMEM_MAIN);

    k_pool <<<BB * CC, 128>>>(cond, pool, counter);
    k_wmat <<<512, 256>>>(w_lin, b_lin, pool, out, diag);
    {
        dim3 gc(4, BB);
        k_cond <<<gc, 256>>>(out, diag, partials, counter, out, out_size);
    }
    {
        dim3 g1(31, BB);                 // tiles 1..31 (never write hw<128)
        k_main <<<g1, 256, SMEM_MAIN>>>(inp, out, 1);
        dim3 g2(1, BB);                  // tile 0 (reads own E before writing)
        k_main <<<g2, 256, SMEM_MAIN>>>(inp, out, 0);
    }
}